// round 1
// baseline (speedup 1.0000x reference)
#include <cuda_runtime.h>
#include <cuda_bf16.h>

// Problem constants
#define NN 2048      // nodes
#define DD 16        // embedding dim
#define BB 64        // batch
#define CC 64        // in channels
#define OO 64        // out channels
#define KK 3         // cheb order
#define KC (KK*CC)   // 192
#define WCOLS (KC*OO) // 12288

// Scratch (static device allocations are allowed)
__device__ float g_A [NN * NN];          // 16 MB: softmax(relu(E E^T))
__device__ float g_Y1[BB * NN * CC];     // 32 MB: A @ feat      (layout [B,N,C])
__device__ float g_Y2[BB * NN * CC];     // 32 MB: 2 A @ Y1 - feat
__device__ float g_W [NN * WCOLS];       // 100 MB: per-node weights [N,192,64]

// ---------------------------------------------------------------------------
// Kernel 1: A[n,:] = softmax(relu(E[n,:] @ E^T)) — one block per row
// ---------------------------------------------------------------------------
__global__ void __launch_bounds__(256) adj_softmax(const float* __restrict__ E)
{
    const int n = blockIdx.x;
    const int t = threadIdx.x;

    __shared__ float row[NN];
    __shared__ float en_s[DD];
    __shared__ float red[256];

    if (t < DD) en_s[t] = E[n * DD + t];
    __syncthreads();

    float e[DD];
#pragma unroll
    for (int d = 0; d < DD; d++) e[d] = en_s[d];

    float lmax = 0.0f;  // relu >= 0
#pragma unroll 4
    for (int m = t; m < NN; m += 256) {
        const float4* Em = reinterpret_cast<const float4*>(E + m * DD);
        float4 v0 = Em[0], v1 = Em[1], v2 = Em[2], v3 = Em[3];
        float s = e[0]*v0.x + e[1]*v0.y + e[2]*v0.z + e[3]*v0.w
                + e[4]*v1.x + e[5]*v1.y + e[6]*v1.z + e[7]*v1.w
                + e[8]*v2.x + e[9]*v2.y + e[10]*v2.z + e[11]*v2.w
                + e[12]*v3.x + e[13]*v3.y + e[14]*v3.z + e[15]*v3.w;
        s = fmaxf(s, 0.0f);
        row[m] = s;
        lmax = fmaxf(lmax, s);
    }

    red[t] = lmax;
    __syncthreads();
#pragma unroll
    for (int off = 128; off > 0; off >>= 1) {
        if (t < off) red[t] = fmaxf(red[t], red[t + off]);
        __syncthreads();
    }
    const float mx = red[0];
    __syncthreads();

    float lsum = 0.0f;
#pragma unroll 4
    for (int m = t; m < NN; m += 256) {
        float v = expf(row[m] - mx);
        row[m] = v;
        lsum += v;
    }
    red[t] = lsum;
    __syncthreads();
#pragma unroll
    for (int off = 128; off > 0; off >>= 1) {
        if (t < off) red[t] += red[t + off];
        __syncthreads();
    }
    const float inv = 1.0f / red[0];

#pragma unroll 4
    for (int m = t; m < NN; m += 256)
        g_A[n * NN + m] = row[m] * inv;
}

// ---------------------------------------------------------------------------
// Kernel 2: per-node weights  g_W[n, kc, o] = sum_d E[n,d] * Wp[d, kc, o]
// grid: (WCOLS/128, NN/64); tiles Wp[16 x 128] and E[64 x 16] in smem
// ---------------------------------------------------------------------------
__global__ void __launch_bounds__(256) compute_weights(
    const float* __restrict__ E, const float* __restrict__ Wp)
{
    const int col0 = blockIdx.x * 128;
    const int n0   = blockIdx.y * 64;
    const int t    = threadIdx.x;

    __shared__ float ws[DD][128];
    __shared__ float es[64][DD];

    {   // Wp tile: 16 x 128 = 2048 floats, 2 float4 per thread
        int r = t / 32;
        int c = (t % 32) * 4;
        *(float4*)&ws[r    ][c] = *(const float4*)(Wp + (size_t)r * WCOLS + col0 + c);
        *(float4*)&ws[r + 8][c] = *(const float4*)(Wp + (size_t)(r + 8) * WCOLS + col0 + c);
    }
    {   // E tile: 64 x 16 = 1024 floats, 1 float4 per thread
        int r = t / 4;
        int c = (t % 4) * 4;
        *(float4*)&es[r][c] = *(const float4*)(E + (n0 + r) * DD + c);
    }
    __syncthreads();

    const int tx = t % 32;     // col group (4 cols)
    const int ty = t / 32;     // n stride 8
#pragma unroll
    for (int nn = ty; nn < 64; nn += 8) {
        float4 acc = make_float4(0.f, 0.f, 0.f, 0.f);
#pragma unroll
        for (int d = 0; d < DD; d++) {
            float ev = es[nn][d];
            float4 w = *(const float4*)&ws[d][tx * 4];
            acc.x += ev * w.x; acc.y += ev * w.y;
            acc.z += ev * w.z; acc.w += ev * w.w;
        }
        *(float4*)(g_W + (size_t)(n0 + nn) * WCOLS + col0 + tx * 4) = acc;
    }
}

// ---------------------------------------------------------------------------
// Kernel 3: batched GEMM.
//   PASS 0: Y1_b = A @ feat_b
//   PASS 1: Y2_b = 2 * (A @ Y1_b) - feat_b
// A: [2048,2048] row-major; feat/Y: [B,N,C] => per-batch [2048 x 64] row-major.
// Tile: 128(M) x 64(N=C) x 32(K). 256 threads, 8x4 register tile each.
// ---------------------------------------------------------------------------
template <int PASS>
__global__ void __launch_bounds__(256) gemm_kernel(const float* __restrict__ feat)
{
    const int b    = blockIdx.z;
    const int row0 = blockIdx.x * 128;
    const int t    = threadIdx.x;

    const float* __restrict__ Xb = (PASS == 0 ? feat : (const float*)g_Y1) + (size_t)b * NN * CC;
    float*       __restrict__ Yb = (PASS == 0 ? g_Y1 : g_Y2)               + (size_t)b * NN * CC;
    const float* __restrict__ Fb = feat + (size_t)b * NN * CC;

    __shared__ float As[32][128 + 4];  // transposed A tile [k][m]
    __shared__ float Xs[32][64];       // X tile [k][c]

    const int tx = t % 16;  // 4 cols each  -> 64
    const int ty = t / 16;  // 8 rows each  -> 128

    float acc[8][4];
#pragma unroll
    for (int i = 0; i < 8; i++)
#pragma unroll
        for (int j = 0; j < 4; j++) acc[i][j] = 0.f;

    for (int k0 = 0; k0 < NN; k0 += 32) {
        {   // A tile: 128 x 32; 4 float4 per thread, stored transposed
            int tr = t / 8;
            int tc = (t % 8) * 4;
#pragma unroll
            for (int p = 0; p < 4; p++) {
                int r = tr + p * 32;
                float4 v = *(const float4*)(g_A + (size_t)(row0 + r) * NN + k0 + tc);
                As[tc + 0][r] = v.x; As[tc + 1][r] = v.y;
                As[tc + 2][r] = v.z; As[tc + 3][r] = v.w;
            }
        }
        {   // X tile: 32 x 64; 2 float4 per thread
            int tr = t / 16;
            int tc = (t % 16) * 4;
#pragma unroll
            for (int p = 0; p < 2; p++) {
                int r = tr + p * 16;
                *(float4*)&Xs[r][tc] = *(const float4*)(Xb + (size_t)(k0 + r) * CC + tc);
            }
        }
        __syncthreads();

#pragma unroll
        for (int k = 0; k < 32; k++) {
            float a[8], x[4];
            *(float4*)&a[0] = *(const float4*)&As[k][ty * 8];
            *(float4*)&a[4] = *(const float4*)&As[k][ty * 8 + 4];
            *(float4*)&x[0] = *(const float4*)&Xs[k][tx * 4];
#pragma unroll
            for (int i = 0; i < 8; i++)
#pragma unroll
                for (int j = 0; j < 4; j++)
                    acc[i][j] += a[i] * x[j];
        }
        __syncthreads();
    }

#pragma unroll
    for (int i = 0; i < 8; i++) {
        const int r = row0 + ty * 8 + i;
        float4 v;
        if (PASS == 0) {
            v.x = acc[i][0]; v.y = acc[i][1]; v.z = acc[i][2]; v.w = acc[i][3];
        } else {
            float4 f = *(const float4*)(Fb + (size_t)r * CC + tx * 4);
            v.x = 2.f * acc[i][0] - f.x; v.y = 2.f * acc[i][1] - f.y;
            v.z = 2.f * acc[i][2] - f.z; v.w = 2.f * acc[i][3] - f.w;
        }
        *(float4*)(Yb + (size_t)r * CC + tx * 4) = v;
    }
}

// ---------------------------------------------------------------------------
// Kernel 4: per-node output  out[b,n,o] = sum_{k,c} X[b,n,k,c] * W_n[kc,o] + bias[n,o]
// X rows gathered from {feat, Y1, Y2}; one block per n; 4x4 register tile.
// ---------------------------------------------------------------------------
__global__ void __launch_bounds__(256) final_gconv(
    const float* __restrict__ feat,
    const float* __restrict__ E,
    const float* __restrict__ biasP,
    float* __restrict__ out)
{
    const int n = blockIdx.x;
    const int t = threadIdx.x;

    __shared__ float Xs[64][68];   // [b][c] for current k-chunk (padded)
    __shared__ float Ws[64][64];   // [kc within chunk][o]
    __shared__ float bias_s[OO];

    if (t < OO) {
        float s = 0.f;
#pragma unroll
        for (int d = 0; d < DD; d++) s += E[n * DD + d] * biasP[d * OO + t];
        bias_s[t] = s;
    }

    const int tx = t % 16;  // o group (4)
    const int ty = t / 16;  // b group (4)

    float acc[4][4];
#pragma unroll
    for (int i = 0; i < 4; i++)
#pragma unroll
        for (int j = 0; j < 4; j++) acc[i][j] = 0.f;

    const float* srcs[KK] = { feat, g_Y1, g_Y2 };

#pragma unroll
    for (int k = 0; k < KK; k++) {
        const float* __restrict__ src = srcs[k];
        {   // X chunk: 64 b x 64 c
            int c4 = (t % 16) * 4;
            int b  = t / 16;
#pragma unroll
            for (int p = 0; p < 4; p++) {
                float4 v = *(const float4*)(src + (size_t)(b + p * 16) * (NN * CC) + n * CC + c4);
                *(float4*)&Xs[b + p * 16][c4] = v;
            }
        }
        {   // W chunk: contiguous 4096 floats
            const float4* wsrc = (const float4*)(g_W + (size_t)n * WCOLS + k * (CC * OO));
            float4* wdst = (float4*)&Ws[0][0];
#pragma unroll
            for (int i = 0; i < 4; i++) wdst[t + i * 256] = wsrc[t + i * 256];
        }
        __syncthreads();

#pragma unroll
        for (int kc = 0; kc < CC; kc++) {
            float4 w = *(const float4*)&Ws[kc][tx * 4];
            float x0 = Xs[ty * 4 + 0][kc];
            float x1 = Xs[ty * 4 + 1][kc];
            float x2 = Xs[ty * 4 + 2][kc];
            float x3 = Xs[ty * 4 + 3][kc];
            acc[0][0] += x0 * w.x; acc[0][1] += x0 * w.y; acc[0][2] += x0 * w.z; acc[0][3] += x0 * w.w;
            acc[1][0] += x1 * w.x; acc[1][1] += x1 * w.y; acc[1][2] += x1 * w.z; acc[1][3] += x1 * w.w;
            acc[2][0] += x2 * w.x; acc[2][1] += x2 * w.y; acc[2][2] += x2 * w.z; acc[2][3] += x2 * w.w;
            acc[3][0] += x3 * w.x; acc[3][1] += x3 * w.y; acc[3][2] += x3 * w.z; acc[3][3] += x3 * w.w;
        }
        __syncthreads();
    }

#pragma unroll
    for (int i = 0; i < 4; i++) {
        const int b = ty * 4 + i;
        float4 v;
        v.x = acc[i][0] + bias_s[tx * 4 + 0];
        v.y = acc[i][1] + bias_s[tx * 4 + 1];
        v.z = acc[i][2] + bias_s[tx * 4 + 2];
        v.w = acc[i][3] + bias_s[tx * 4 + 3];
        *(float4*)(out + (size_t)b * (NN * OO) + n * OO + tx * 4) = v;
    }
}

// ---------------------------------------------------------------------------
extern "C" void kernel_launch(void* const* d_in, const int* in_sizes, int n_in,
                              void* d_out, int out_size)
{
    const float* E     = (const float*)d_in[0];  // [2048,16]
    const float* feat  = (const float*)d_in[1];  // [64,2048,64]
    const float* Wp    = (const float*)d_in[2];  // [16,3,64,64]
    const float* biasP = (const float*)d_in[3];  // [16,64]
    float* out = (float*)d_out;                  // [64,2048,64]

    adj_softmax<<<NN, 256>>>(E);
    compute_weights<<<dim3(WCOLS / 128, NN / 64), 256>>>(E, Wp);
    gemm_kernel<0><<<dim3(NN / 128, 1, BB), 256>>>(feat);
    gemm_kernel<1><<<dim3(NN / 128, 1, BB), 256>>>(feat);
    final_gconv<<<NN, 256>>>(feat, E, biasP, out);
}

// round 3
// speedup vs baseline: 4.2548x; 4.2548x over previous
#include <cuda_runtime.h>
#include <cuda_fp16.h>
#include <cstdint>

// Problem constants
#define NN 2048      // nodes
#define DD 16        // embedding dim
#define BB 64        // batch
#define CC 64        // in channels
#define OO 64        // out channels
#define KK 3         // cheb order
#define KC (KK*CC)   // 192
#define WCOLS (KC*OO) // 12288
#define BC (BB*CC)   // 4096 columns of the big GEMM

// ---------------- scratch (static device allocations allowed) ----------------
__device__ __half g_Ah  [(size_t)NN * NN];    // 8 MB : softmax(relu(E E^T)) fp16
__device__ __half g_XTh [(size_t)BC * NN];    // 16 MB: XT[bc][m] = feat[b][m][c] fp16
__device__ __half g_Y1Th[(size_t)BC * NN];    // 16 MB: Y1 transposed fp16 (pass-1 B)
__device__ float  g_Y1 [(size_t)BB * NN * CC]; // 32 MB : [B,N,C]
__device__ float  g_Y2 [(size_t)BB * NN * CC]; // 32 MB : [B,N,C]
__device__ float  g_W  [(size_t)NN * WCOLS];   // 100 MB : per-node weights

// ---------------- PTX helpers (baseline ISA only: sm_80-era) ----------------
__device__ __forceinline__ uint32_t smem_u32(const void* p) {
    uint32_t a;
    asm("{ .reg .u64 t; cvta.to.shared.u64 t, %1; cvt.u32.u64 %0, t; }" : "=r"(a) : "l"(p));
    return a;
}
#define CP_ASYNC16(dst, src) \
    asm volatile("cp.async.cg.shared.global [%0], [%1], 16;" :: "r"(dst), "l"(src))
#define CP_COMMIT() asm volatile("cp.async.commit_group;" ::: "memory")
#define CP_WAIT1()  asm volatile("cp.async.wait_group 1;" ::: "memory")
#define CP_WAIT0()  asm volatile("cp.async.wait_group 0;" ::: "memory")

__device__ __forceinline__ void ldsm4(uint32_t* r, uint32_t addr) {
    asm volatile("ldmatrix.sync.aligned.m8n8.x4.shared.b16 {%0,%1,%2,%3}, [%4];"
        : "=r"(r[0]), "=r"(r[1]), "=r"(r[2]), "=r"(r[3]) : "r"(addr));
}
__device__ __forceinline__ void mma16816(float* d, const uint32_t* a, const uint32_t* b) {
    asm volatile("mma.sync.aligned.m16n8k16.row.col.f32.f16.f16.f32 "
        "{%0,%1,%2,%3}, {%4,%5,%6,%7}, {%8,%9}, {%0,%1,%2,%3};"
        : "+f"(d[0]), "+f"(d[1]), "+f"(d[2]), "+f"(d[3])
        : "r"(a[0]), "r"(a[1]), "r"(a[2]), "r"(a[3]), "r"(b[0]), "r"(b[1]));
}
#define SWZ(o) ((o) ^ (((o) >> 3) & 0x70))

// ---------------------------------------------------------------------------
// Kernel 1: A[n,:] = softmax(relu(E[n,:] @ E^T)) -> fp16
// ---------------------------------------------------------------------------
__global__ void __launch_bounds__(256) adj_softmax(const float* __restrict__ E)
{
    const int n = blockIdx.x;
    const int t = threadIdx.x;

    __shared__ float row[NN];
    __shared__ float en_s[DD];
    __shared__ float red[256];

    if (t < DD) en_s[t] = E[n * DD + t];
    __syncthreads();

    float e[DD];
#pragma unroll
    for (int d = 0; d < DD; d++) e[d] = en_s[d];

    float lmax = 0.0f;
#pragma unroll 4
    for (int m = t; m < NN; m += 256) {
        const float4* Em = reinterpret_cast<const float4*>(E + m * DD);
        float4 v0 = Em[0], v1 = Em[1], v2 = Em[2], v3 = Em[3];
        float s = e[0]*v0.x + e[1]*v0.y + e[2]*v0.z + e[3]*v0.w
                + e[4]*v1.x + e[5]*v1.y + e[6]*v1.z + e[7]*v1.w
                + e[8]*v2.x + e[9]*v2.y + e[10]*v2.z + e[11]*v2.w
                + e[12]*v3.x + e[13]*v3.y + e[14]*v3.z + e[15]*v3.w;
        s = fmaxf(s, 0.0f);
        row[m] = s;
        lmax = fmaxf(lmax, s);
    }
    red[t] = lmax;
    __syncthreads();
#pragma unroll
    for (int off = 128; off > 0; off >>= 1) {
        if (t < off) red[t] = fmaxf(red[t], red[t + off]);
        __syncthreads();
    }
    const float mx = red[0];
    __syncthreads();

    float lsum = 0.0f;
#pragma unroll 4
    for (int m = t; m < NN; m += 256) {
        float v = expf(row[m] - mx);
        row[m] = v;
        lsum += v;
    }
    red[t] = lsum;
    __syncthreads();
#pragma unroll
    for (int off = 128; off > 0; off >>= 1) {
        if (t < off) red[t] += red[t + off];
        __syncthreads();
    }
    const float inv = 1.0f / red[0];

#pragma unroll 4
    for (int m = t; m < NN; m += 256)
        g_Ah[(size_t)n * NN + m] = __float2half(row[m] * inv);
}

// ---------------------------------------------------------------------------
// Kernel 2: transpose feat [B,N,C] fp32 -> XT [bc][m] fp16
// ---------------------------------------------------------------------------
__global__ void __launch_bounds__(256) feat_transpose(const float* __restrict__ feat)
{
    const int m0 = blockIdx.x * 64;
    const int b  = blockIdx.y;
    const int t  = threadIdx.x;
    __shared__ float tile[64][65];

    const int mr = t >> 4, c4 = (t & 15) * 4;
#pragma unroll
    for (int p = 0; p < 4; p++) {
        float4 v = *(const float4*)(feat + ((size_t)b * NN + m0 + mr + p * 16) * CC + c4);
        tile[mr + p * 16][c4 + 0] = v.x;
        tile[mr + p * 16][c4 + 1] = v.y;
        tile[mr + p * 16][c4 + 2] = v.z;
        tile[mr + p * 16][c4 + 3] = v.w;
    }
    __syncthreads();

    const int cl = t >> 4, m4 = (t & 15) * 4;
#pragma unroll
    for (int p = 0; p < 4; p++) {
        int c = cl + p * 16;
        __half2 p0 = __floats2half2_rn(tile[m4 + 0][c], tile[m4 + 1][c]);
        __half2 p1 = __floats2half2_rn(tile[m4 + 2][c], tile[m4 + 3][c]);
        *(uint2*)(g_XTh + (size_t)(b * 64 + c) * NN + m0 + m4) =
            make_uint2(*(uint32_t*)&p0, *(uint32_t*)&p1);
    }
}

// ---------------------------------------------------------------------------
// Kernel 3: per-node weights  g_W[n, kc, o] = sum_d E[n,d] * Wp[d, kc, o]
// ---------------------------------------------------------------------------
__global__ void __launch_bounds__(256) compute_weights(
    const float* __restrict__ E, const float* __restrict__ Wp)
{
    const int col0 = blockIdx.x * 128;
    const int n0   = blockIdx.y * 64;
    const int t    = threadIdx.x;

    __shared__ float ws[DD][128];
    __shared__ float es[64][DD];

    {
        int r = t / 32;
        int c = (t % 32) * 4;
        *(float4*)&ws[r    ][c] = *(const float4*)(Wp + (size_t)r * WCOLS + col0 + c);
        *(float4*)&ws[r + 8][c] = *(const float4*)(Wp + (size_t)(r + 8) * WCOLS + col0 + c);
    }
    {
        int r = t / 4;
        int c = (t % 4) * 4;
        *(float4*)&es[r][c] = *(const float4*)(E + (n0 + r) * DD + c);
    }
    __syncthreads();

    const int tx = t % 32;
    const int ty = t / 32;
#pragma unroll
    for (int nn = ty; nn < 64; nn += 8) {
        float4 acc = make_float4(0.f, 0.f, 0.f, 0.f);
#pragma unroll
        for (int d = 0; d < DD; d++) {
            float ev = es[nn][d];
            float4 w = *(const float4*)&ws[d][tx * 4];
            acc.x += ev * w.x; acc.y += ev * w.y;
            acc.z += ev * w.z; acc.w += ev * w.w;
        }
        *(float4*)(g_W + (size_t)(n0 + nn) * WCOLS + col0 + tx * 4) = acc;
    }
}

// ---------------------------------------------------------------------------
// Kernel 4: mma.sync fp16 GEMM.  D[n, bc] = sum_m A[n,m] * B[bc, m]
//   PASS 0: B = g_XTh ; writes g_Y1 [B,N,C] fp32 and g_Y1Th [bc][m] fp16
//   PASS 1: B = g_Y1Th; writes g_Y2 = 2*D - feat  fp32
// CTA tile 128x128, K-chunk 64 (=128B swizzle row), 3-stage cp.async pipeline.
// 8 warps (2m x 4n), warp tile 64x32, mma.m16n8k16.
// ---------------------------------------------------------------------------
#define MT 128
#define NT 128
#define KCH 64
#define NCH (NN / KCH)     // 32
#define ASTG (MT * 128)    // 16 KB
#define BSTG (NT * 128)    // 16 KB
#define STG_BYTES (ASTG + BSTG)
#define STAGES 3
#define EPI_PITCH 132
#define GEMM_SMEM (STAGES * STG_BYTES + 1024)

template <int PASS>
__global__ void __launch_bounds__(256, 2) gemm_mma(const float* __restrict__ feat)
{
    extern __shared__ char smem_raw[];
    char* sal = (char*)(((uintptr_t)smem_raw + 1023) & ~(uintptr_t)1023);
    const uint32_t sb = smem_u32(sal);

    const int t    = threadIdx.x;
    const int lane = t & 31;
    const int wid  = t >> 5;
    const int wm   = wid >> 2;   // 0..1
    const int wn   = wid & 3;    // 0..3
    const int m0   = blockIdx.x * MT;
    const int n0   = blockIdx.y * NT;

    const __half* __restrict__ Bsrc = PASS ? g_Y1Th : g_XTh;

    float acc[4][4][4];
#pragma unroll
    for (int i = 0; i < 4; i++)
#pragma unroll
        for (int j = 0; j < 4; j++)
#pragma unroll
            for (int q = 0; q < 4; q++) acc[i][j][q] = 0.f;

    // ---- async load of chunk ch into stage s ----
    auto load_chunk = [&](int ch, int s) {
        const uint32_t stA = sb + s * STG_BYTES;
        const uint32_t stB = stA + ASTG;
        const __half* agp = g_Ah + (size_t)m0 * NN + ch * KCH;
        const __half* bgp = Bsrc + (size_t)n0 * NN + ch * KCH;
#pragma unroll
        for (int i = 0; i < 4; i++) {
            int idx = t + i * 256;
            int r = idx >> 3, c = idx & 7;
            uint32_t so = SWZ((uint32_t)(r * 128 + c * 16));
            CP_ASYNC16(stA + so, agp + (size_t)r * NN + c * 8);
            CP_ASYNC16(stB + so, bgp + (size_t)r * NN + c * 8);
        }
        CP_COMMIT();
    };

    load_chunk(0, 0);
    load_chunk(1, 1);

    // lane-derived ldmatrix address components
    const int a_row  = (lane & 15);            // + wm*64 + mf*16
    const int a_kofs = (lane >> 4) << 4;       // bytes
    const int b_row  = ((lane >> 4) << 3) + (lane & 7);  // + wn*32 + nf2*16
    const int b_kofs = ((lane >> 3) & 1) << 4; // bytes

    for (int ch = 0; ch < NCH; ch++) {
        const int s = ch % STAGES;
        if (ch >= NCH - 2) { CP_WAIT0(); } else { CP_WAIT1(); }
        __syncthreads();
        if (ch + 2 < NCH) load_chunk(ch + 2, (ch + 2) % STAGES);

        const uint32_t stA = sb + s * STG_BYTES;
        const uint32_t stB = stA + ASTG;
#pragma unroll
        for (int kk = 0; kk < 4; kk++) {
            uint32_t a[4][4], b[2][4];
#pragma unroll
            for (int mf = 0; mf < 4; mf++) {
                int r = wm * 64 + mf * 16 + a_row;
                ldsm4(a[mf], stA + SWZ((uint32_t)(r * 128 + kk * 32 + a_kofs)));
            }
#pragma unroll
            for (int nf2 = 0; nf2 < 2; nf2++) {
                int r = wn * 32 + nf2 * 16 + b_row;
                ldsm4(b[nf2], stB + SWZ((uint32_t)(r * 128 + kk * 32 + b_kofs)));
            }
#pragma unroll
            for (int mf = 0; mf < 4; mf++)
#pragma unroll
                for (int nf = 0; nf < 4; nf++)
                    mma16816(acc[mf][nf], a[mf], &b[nf >> 1][(nf & 1) * 2]);
        }
        __syncthreads();
    }

    // ---- epilogue: stage accumulators through smem (fp32, padded pitch) ----
    float* esm = (float*)sal;
#pragma unroll
    for (int mf = 0; mf < 4; mf++) {
#pragma unroll
        for (int nf = 0; nf < 4; nf++) {
            int r = wm * 64 + mf * 16 + (lane >> 2);
            int c = wn * 32 + nf * 8 + (lane & 3) * 2;
            esm[r * EPI_PITCH + c]           = acc[mf][nf][0];
            esm[r * EPI_PITCH + c + 1]       = acc[mf][nf][1];
            esm[(r + 8) * EPI_PITCH + c]     = acc[mf][nf][2];
            esm[(r + 8) * EPI_PITCH + c + 1] = acc[mf][nf][3];
        }
    }
    __syncthreads();

    const int r = t >> 1;          // 0..127 (row / col index)
    const int h = t & 1;           // half selector
    if (PASS == 0) {
        {   // g_Y1 fp32 [B,N,C]: row r = node, cols h*64..h*64+63 (one b)
            const int n = m0 + r;
            const int b = (n0 >> 6) + h;
            float4* dst = (float4*)(g_Y1 + ((size_t)b * NN + n) * CC);
#pragma unroll
            for (int i = 0; i < 16; i++)
                dst[i] = *(float4*)&esm[r * EPI_PITCH + h * 64 + i * 4];
        }
        {   // g_Y1Th fp16 [bc][m]: col j = bc, rows h*64.. (smem column read)
            const int j = r;
            __half* d2 = g_Y1Th + (size_t)(n0 + j) * NN + m0 + h * 64;
#pragma unroll
            for (int i = 0; i < 64; i += 2) {
                __half2 hv = __floats2half2_rn(esm[(h * 64 + i) * EPI_PITCH + j],
                                               esm[(h * 64 + i + 1) * EPI_PITCH + j]);
                *(__half2*)(d2 + i) = hv;
            }
        }
    } else {
        const int n = m0 + r;
        const int b = (n0 >> 6) + h;
        const float4* fsrc = (const float4*)(feat + ((size_t)b * NN + n) * CC);
        float4* dst = (float4*)(g_Y2 + ((size_t)b * NN + n) * CC);
#pragma unroll
        for (int i = 0; i < 16; i++) {
            float4 a4 = *(float4*)&esm[r * EPI_PITCH + h * 64 + i * 4];
            float4 f  = fsrc[i];
            float4 v;
            v.x = 2.f * a4.x - f.x; v.y = 2.f * a4.y - f.y;
            v.z = 2.f * a4.z - f.z; v.w = 2.f * a4.w - f.w;
            dst[i] = v;
        }
    }
}

// ---------------------------------------------------------------------------
// Kernel 5: per-node output  out[b,n,o] = sum_{k,c} X[b,n,k,c] * W_n[kc,o] + bias
// ---------------------------------------------------------------------------
__global__ void __launch_bounds__(256) final_gconv(
    const float* __restrict__ feat,
    const float* __restrict__ E,
    const float* __restrict__ biasP,
    float* __restrict__ out)
{
    const int n = blockIdx.x;
    const int t = threadIdx.x;

    __shared__ float Xs[64][68];
    __shared__ float Ws[64][64];
    __shared__ float bias_s[OO];

    if (t < OO) {
        float s = 0.f;
#pragma unroll
        for (int d = 0; d < DD; d++) s += E[n * DD + d] * biasP[d * OO + t];
        bias_s[t] = s;
    }

    const int tx = t % 16;
    const int ty = t / 16;

    float acc[4][4];
#pragma unroll
    for (int i = 0; i < 4; i++)
#pragma unroll
        for (int j = 0; j < 4; j++) acc[i][j] = 0.f;

    const float* srcs[KK] = { feat, g_Y1, g_Y2 };

#pragma unroll
    for (int k = 0; k < KK; k++) {
        const float* __restrict__ src = srcs[k];
        {
            int c4 = (t % 16) * 4;
            int b  = t / 16;
#pragma unroll
            for (int p = 0; p < 4; p++) {
                float4 v = *(const float4*)(src + (size_t)(b + p * 16) * (NN * CC) + n * CC + c4);
                *(float4*)&Xs[b + p * 16][c4] = v;
            }
        }
        {
            const float4* wsrc = (const float4*)(g_W + (size_t)n * WCOLS + k * (CC * OO));
            float4* wdst = (float4*)&Ws[0][0];
#pragma unroll
            for (int i = 0; i < 4; i++) wdst[t + i * 256] = wsrc[t + i * 256];
        }
        __syncthreads();

#pragma unroll
        for (int kc = 0; kc < CC; kc++) {
            float4 w = *(const float4*)&Ws[kc][tx * 4];
            float x0 = Xs[ty * 4 + 0][kc];
            float x1 = Xs[ty * 4 + 1][kc];
            float x2 = Xs[ty * 4 + 2][kc];
            float x3 = Xs[ty * 4 + 3][kc];
            acc[0][0] += x0 * w.x; acc[0][1] += x0 * w.y; acc[0][2] += x0 * w.z; acc[0][3] += x0 * w.w;
            acc[1][0] += x1 * w.x; acc[1][1] += x1 * w.y; acc[1][2] += x1 * w.z; acc[1][3] += x1 * w.w;
            acc[2][0] += x2 * w.x; acc[2][1] += x2 * w.y; acc[2][2] += x2 * w.z; acc[2][3] += x2 * w.w;
            acc[3][0] += x3 * w.x; acc[3][1] += x3 * w.y; acc[3][2] += x3 * w.z; acc[3][3] += x3 * w.w;
        }
        __syncthreads();
    }

#pragma unroll
    for (int i = 0; i < 4; i++) {
        const int b = ty * 4 + i;
        float4 v;
        v.x = acc[i][0] + bias_s[tx * 4 + 0];
        v.y = acc[i][1] + bias_s[tx * 4 + 1];
        v.z = acc[i][2] + bias_s[tx * 4 + 2];
        v.w = acc[i][3] + bias_s[tx * 4 + 3];
        *(float4*)(out + (size_t)b * (NN * OO) + n * OO + tx * 4) = v;
    }
}

// ---------------------------------------------------------------------------
extern "C" void kernel_launch(void* const* d_in, const int* in_sizes, int n_in,
                              void* d_out, int out_size)
{
    const float* E     = (const float*)d_in[0];  // [2048,16]
    const float* feat  = (const float*)d_in[1];  // [64,2048,64]
    const float* Wp    = (const float*)d_in[2];  // [16,3,64,64]
    const float* biasP = (const float*)d_in[3];  // [16,64]
    float* out = (float*)d_out;                  // [64,2048,64]

    cudaFuncSetAttribute(gemm_mma<0>, cudaFuncAttributeMaxDynamicSharedMemorySize, GEMM_SMEM);
    cudaFuncSetAttribute(gemm_mma<1>, cudaFuncAttributeMaxDynamicSharedMemorySize, GEMM_SMEM);

    adj_softmax<<<NN, 256>>>(E);
    feat_transpose<<<dim3(NN / 64, BB), 256>>>(feat);
    compute_weights<<<dim3(WCOLS / 128, NN / 64), 256>>>(E, Wp);
    gemm_mma<0><<<dim3(NN / MT, BC / NT), 256, GEMM_SMEM>>>(feat);
    gemm_mma<1><<<dim3(NN / MT, BC / NT), 256, GEMM_SMEM>>>(feat);
    final_gconv<<<NN, 256>>>(feat, E, biasP, out);
}

// round 4
// speedup vs baseline: 4.6709x; 1.0978x over previous
#include <cuda_runtime.h>
#include <cuda_fp16.h>
#include <cstdint>

// Problem constants
#define NN 2048      // nodes
#define DD 16        // embedding dim
#define BB 64        // batch
#define CC 64        // in channels
#define OO 64        // out channels
#define KK 3         // cheb order
#define KC (KK*CC)   // 192
#define WCOLS (KC*OO) // 12288
#define BC (BB*CC)   // 4096 columns of the big GEMM

// ---------------- scratch (static device allocations allowed) ----------------
__device__ __half g_Ah  [(size_t)NN * NN];     // 8 MB : softmax(relu(E E^T)) fp16
__device__ __half g_XTh [(size_t)BC * NN];     // 16 MB: XT[bc][m] = feat[b][m][c]
__device__ __half g_Y1Th[(size_t)BC * NN];     // 16 MB: Y1 transposed (pass-1 B)
__device__ __half g_Fh  [(size_t)BB * NN * CC]; // 16 MB: feat fp16 [B,N,C]
__device__ __half g_Y1h [(size_t)BB * NN * CC]; // 16 MB: Y1  fp16 [B,N,C]
__device__ __half g_Y2h [(size_t)BB * NN * CC]; // 16 MB: Y2  fp16 [B,N,C]
__device__ __half g_Wh  [(size_t)NN * WCOLS];   // 50 MB: per-node weights fp16 [n][kc][o]

// ---------------- PTX helpers (baseline ISA only) ----------------
__device__ __forceinline__ uint32_t smem_u32(const void* p) {
    uint32_t a;
    asm("{ .reg .u64 t; cvta.to.shared.u64 t, %1; cvt.u32.u64 %0, t; }" : "=r"(a) : "l"(p));
    return a;
}
#define CP_ASYNC16(dst, src) \
    asm volatile("cp.async.cg.shared.global [%0], [%1], 16;" :: "r"(dst), "l"(src))
#define CP_COMMIT() asm volatile("cp.async.commit_group;" ::: "memory")
#define CP_WAIT1()  asm volatile("cp.async.wait_group 1;" ::: "memory")
#define CP_WAIT0()  asm volatile("cp.async.wait_group 0;" ::: "memory")

__device__ __forceinline__ void ldsm4(uint32_t* r, uint32_t addr) {
    asm volatile("ldmatrix.sync.aligned.m8n8.x4.shared.b16 {%0,%1,%2,%3}, [%4];"
        : "=r"(r[0]), "=r"(r[1]), "=r"(r[2]), "=r"(r[3]) : "r"(addr));
}
__device__ __forceinline__ void ldsm4t(uint32_t* r, uint32_t addr) {
    asm volatile("ldmatrix.sync.aligned.m8n8.x4.trans.shared.b16 {%0,%1,%2,%3}, [%4];"
        : "=r"(r[0]), "=r"(r[1]), "=r"(r[2]), "=r"(r[3]) : "r"(addr));
}
__device__ __forceinline__ void mma16816(float* d, const uint32_t* a, const uint32_t* b) {
    asm volatile("mma.sync.aligned.m16n8k16.row.col.f32.f16.f16.f32 "
        "{%0,%1,%2,%3}, {%4,%5,%6,%7}, {%8,%9}, {%0,%1,%2,%3};"
        : "+f"(d[0]), "+f"(d[1]), "+f"(d[2]), "+f"(d[3])
        : "r"(a[0]), "r"(a[1]), "r"(a[2]), "r"(a[3]), "r"(b[0]), "r"(b[1]));
}
#define SWZ(o) ((o) ^ (((o) >> 3) & 0x70))

// ---------------------------------------------------------------------------
// Kernel 1: A[n,:] = softmax(relu(E[n,:] @ E^T)) -> fp16
// ---------------------------------------------------------------------------
__global__ void __launch_bounds__(256) adj_softmax(const float* __restrict__ E)
{
    const int n = blockIdx.x;
    const int t = threadIdx.x;

    __shared__ float row[NN];
    __shared__ float en_s[DD];
    __shared__ float red[256];

    if (t < DD) en_s[t] = E[n * DD + t];
    __syncthreads();

    float e[DD];
#pragma unroll
    for (int d = 0; d < DD; d++) e[d] = en_s[d];

    float lmax = 0.0f;
#pragma unroll 4
    for (int m = t; m < NN; m += 256) {
        const float4* Em = reinterpret_cast<const float4*>(E + m * DD);
        float4 v0 = Em[0], v1 = Em[1], v2 = Em[2], v3 = Em[3];
        float s = e[0]*v0.x + e[1]*v0.y + e[2]*v0.z + e[3]*v0.w
                + e[4]*v1.x + e[5]*v1.y + e[6]*v1.z + e[7]*v1.w
                + e[8]*v2.x + e[9]*v2.y + e[10]*v2.z + e[11]*v2.w
                + e[12]*v3.x + e[13]*v3.y + e[14]*v3.z + e[15]*v3.w;
        s = fmaxf(s, 0.0f);
        row[m] = s;
        lmax = fmaxf(lmax, s);
    }
    red[t] = lmax;
    __syncthreads();
#pragma unroll
    for (int off = 128; off > 0; off >>= 1) {
        if (t < off) red[t] = fmaxf(red[t], red[t + off]);
        __syncthreads();
    }
    const float mx = red[0];
    __syncthreads();

    float lsum = 0.0f;
#pragma unroll 4
    for (int m = t; m < NN; m += 256) {
        float v = expf(row[m] - mx);
        row[m] = v;
        lsum += v;
    }
    red[t] = lsum;
    __syncthreads();
#pragma unroll
    for (int off = 128; off > 0; off >>= 1) {
        if (t < off) red[t] += red[t + off];
        __syncthreads();
    }
    const float inv = 1.0f / red[0];

#pragma unroll 4
    for (int m = t; m < NN; m += 256)
        g_Ah[(size_t)n * NN + m] = __float2half(row[m] * inv);
}

// ---------------------------------------------------------------------------
// Kernel 2: feat [B,N,C] fp32 -> XT [bc][m] fp16  AND  feat_h [B,N,C] fp16
// ---------------------------------------------------------------------------
__global__ void __launch_bounds__(256) feat_transpose(const float* __restrict__ feat)
{
    const int m0 = blockIdx.x * 64;
    const int b  = blockIdx.y;
    const int t  = threadIdx.x;
    __shared__ float tile[64][65];

    const int mr = t >> 4, c4 = (t & 15) * 4;
#pragma unroll
    for (int p = 0; p < 4; p++) {
        const int m = m0 + mr + p * 16;
        float4 v = *(const float4*)(feat + ((size_t)b * NN + m) * CC + c4);
        tile[mr + p * 16][c4 + 0] = v.x;
        tile[mr + p * 16][c4 + 1] = v.y;
        tile[mr + p * 16][c4 + 2] = v.z;
        tile[mr + p * 16][c4 + 3] = v.w;
        __half2 h0 = __floats2half2_rn(v.x, v.y);
        __half2 h1 = __floats2half2_rn(v.z, v.w);
        *(uint2*)(g_Fh + ((size_t)b * NN + m) * CC + c4) =
            make_uint2(*(uint32_t*)&h0, *(uint32_t*)&h1);
    }
    __syncthreads();

    const int cl = t >> 4, m4 = (t & 15) * 4;
#pragma unroll
    for (int p = 0; p < 4; p++) {
        int c = cl + p * 16;
        __half2 p0 = __floats2half2_rn(tile[m4 + 0][c], tile[m4 + 1][c]);
        __half2 p1 = __floats2half2_rn(tile[m4 + 2][c], tile[m4 + 3][c]);
        *(uint2*)(g_XTh + (size_t)(b * 64 + c) * NN + m0 + m4) =
            make_uint2(*(uint32_t*)&p0, *(uint32_t*)&p1);
    }
}

// ---------------------------------------------------------------------------
// Kernel 3: per-node weights  g_Wh[n, kc, o] = fp16( sum_d E[n,d] * Wp[d, kc, o] )
// ---------------------------------------------------------------------------
__global__ void __launch_bounds__(256) compute_weights(
    const float* __restrict__ E, const float* __restrict__ Wp)
{
    const int col0 = blockIdx.x * 128;
    const int n0   = blockIdx.y * 64;
    const int t    = threadIdx.x;

    __shared__ float ws[DD][128];
    __shared__ float es[64][DD];

    {
        int r = t / 32;
        int c = (t % 32) * 4;
        *(float4*)&ws[r    ][c] = *(const float4*)(Wp + (size_t)r * WCOLS + col0 + c);
        *(float4*)&ws[r + 8][c] = *(const float4*)(Wp + (size_t)(r + 8) * WCOLS + col0 + c);
    }
    {
        int r = t / 4;
        int c = (t % 4) * 4;
        *(float4*)&es[r][c] = *(const float4*)(E + (n0 + r) * DD + c);
    }
    __syncthreads();

    const int tx = t % 32;
    const int ty = t / 32;
#pragma unroll
    for (int nn = ty; nn < 64; nn += 8) {
        float4 acc = make_float4(0.f, 0.f, 0.f, 0.f);
#pragma unroll
        for (int d = 0; d < DD; d++) {
            float ev = es[nn][d];
            float4 w = *(const float4*)&ws[d][tx * 4];
            acc.x += ev * w.x; acc.y += ev * w.y;
            acc.z += ev * w.z; acc.w += ev * w.w;
        }
        __half2 h0 = __floats2half2_rn(acc.x, acc.y);
        __half2 h1 = __floats2half2_rn(acc.z, acc.w);
        *(uint2*)(g_Wh + (size_t)(n0 + nn) * WCOLS + col0 + tx * 4) =
            make_uint2(*(uint32_t*)&h0, *(uint32_t*)&h1);
    }
}

// ---------------------------------------------------------------------------
// Kernel 4: mma.sync fp16 GEMM.  D[n, bc] = sum_m A[n,m] * B[bc, m]
//   PASS 0: B = g_XTh ; writes g_Y1h [B,N,C] fp16 and g_Y1Th [bc][m] fp16
//   PASS 1: B = g_Y1Th; writes g_Y2h = fp16(2*D - feat)
// CTA 128x128, K-chunk 64, 3-stage cp.async, ONE barrier per chunk.
// ---------------------------------------------------------------------------
#define MT 128
#define NT 128
#define KCH 64
#define NCH (NN / KCH)     // 32
#define ASTG (MT * 128)    // 16 KB
#define BSTG (NT * 128)    // 16 KB
#define STG_BYTES (ASTG + BSTG)
#define STAGES 3
#define EPI_PITCH 132
#define GEMM_SMEM (STAGES * STG_BYTES + 1024)

template <int PASS>
__global__ void __launch_bounds__(256, 2) gemm_mma(const float* __restrict__ feat)
{
    extern __shared__ char smem_raw[];
    char* sal = (char*)(((uintptr_t)smem_raw + 1023) & ~(uintptr_t)1023);
    const uint32_t sb = smem_u32(sal);

    const int t    = threadIdx.x;
    const int lane = t & 31;
    const int wid  = t >> 5;
    const int wm   = wid >> 2;   // 0..1
    const int wn   = wid & 3;    // 0..3
    const int m0   = blockIdx.x * MT;
    const int n0   = blockIdx.y * NT;

    const __half* __restrict__ Bsrc = PASS ? g_Y1Th : g_XTh;

    float acc[4][4][4];
#pragma unroll
    for (int i = 0; i < 4; i++)
#pragma unroll
        for (int j = 0; j < 4; j++)
#pragma unroll
            for (int q = 0; q < 4; q++) acc[i][j][q] = 0.f;

    auto load_chunk = [&](int ch, int s) {
        const uint32_t stA = sb + s * STG_BYTES;
        const uint32_t stB = stA + ASTG;
        const __half* agp = g_Ah + (size_t)m0 * NN + ch * KCH;
        const __half* bgp = Bsrc + (size_t)n0 * NN + ch * KCH;
#pragma unroll
        for (int i = 0; i < 4; i++) {
            int idx = t + i * 256;
            int r = idx >> 3, c = idx & 7;
            uint32_t so = SWZ((uint32_t)(r * 128 + c * 16));
            CP_ASYNC16(stA + so, agp + (size_t)r * NN + c * 8);
            CP_ASYNC16(stB + so, bgp + (size_t)r * NN + c * 8);
        }
        CP_COMMIT();
    };

    load_chunk(0, 0);
    load_chunk(1, 1);

    const int a_row  = (lane & 15);
    const int a_kofs = (lane >> 4) << 4;
    const int b_row  = ((lane >> 4) << 3) + (lane & 7);
    const int b_kofs = ((lane >> 3) & 1) << 4;

    for (int ch = 0; ch < NCH; ch++) {
        const int s = ch % STAGES;
        if (ch >= NCH - 2) { CP_WAIT0(); } else { CP_WAIT1(); }
        __syncthreads();
        if (ch + 2 < NCH) load_chunk(ch + 2, (ch + 2) % STAGES);

        const uint32_t stA = sb + s * STG_BYTES;
        const uint32_t stB = stA + ASTG;
#pragma unroll
        for (int kk = 0; kk < 4; kk++) {
            uint32_t a[4][4], b[2][4];
#pragma unroll
            for (int mf = 0; mf < 4; mf++) {
                int r = wm * 64 + mf * 16 + a_row;
                ldsm4(a[mf], stA + SWZ((uint32_t)(r * 128 + kk * 32 + a_kofs)));
            }
#pragma unroll
            for (int nf2 = 0; nf2 < 2; nf2++) {
                int r = wn * 32 + nf2 * 16 + b_row;
                ldsm4(b[nf2], stB + SWZ((uint32_t)(r * 128 + kk * 32 + b_kofs)));
            }
#pragma unroll
            for (int mf = 0; mf < 4; mf++)
#pragma unroll
                for (int nf = 0; nf < 4; nf++)
                    mma16816(acc[mf][nf], a[mf], &b[nf >> 1][(nf & 1) * 2]);
        }
    }
    __syncthreads();   // protect smem before epilogue staging

    // ---- epilogue: stage accumulators through smem (fp32) ----
    float* esm = (float*)sal;
#pragma unroll
    for (int mf = 0; mf < 4; mf++) {
#pragma unroll
        for (int nf = 0; nf < 4; nf++) {
            int r = wm * 64 + mf * 16 + (lane >> 2);
            int c = wn * 32 + nf * 8 + (lane & 3) * 2;
            esm[r * EPI_PITCH + c]           = acc[mf][nf][0];
            esm[r * EPI_PITCH + c + 1]       = acc[mf][nf][1];
            esm[(r + 8) * EPI_PITCH + c]     = acc[mf][nf][2];
            esm[(r + 8) * EPI_PITCH + c + 1] = acc[mf][nf][3];
        }
    }
    __syncthreads();

    const int r = t >> 1;          // 0..127
    const int h = t & 1;
    const int n = m0 + r;
    const int b = (n0 >> 6) + h;
    if (PASS == 0) {
        {   // g_Y1h fp16 [B,N,C]
            __half* dst = g_Y1h + ((size_t)b * NN + n) * CC;
#pragma unroll
            for (int i = 0; i < 16; i++) {
                float4 v = *(float4*)&esm[r * EPI_PITCH + h * 64 + i * 4];
                __half2 h0 = __floats2half2_rn(v.x, v.y);
                __half2 h1 = __floats2half2_rn(v.z, v.w);
                *(uint2*)(dst + i * 4) = make_uint2(*(uint32_t*)&h0, *(uint32_t*)&h1);
            }
        }
        {   // g_Y1Th fp16 [bc][m]
            const int j = r;
            __half* d2 = g_Y1Th + (size_t)(n0 + j) * NN + m0 + h * 64;
#pragma unroll
            for (int i = 0; i < 64; i += 2) {
                __half2 hv = __floats2half2_rn(esm[(h * 64 + i) * EPI_PITCH + j],
                                               esm[(h * 64 + i + 1) * EPI_PITCH + j]);
                *(__half2*)(d2 + i) = hv;
            }
        }
    } else {
        const float4* fsrc = (const float4*)(feat + ((size_t)b * NN + n) * CC);
        __half* dst = g_Y2h + ((size_t)b * NN + n) * CC;
#pragma unroll
        for (int i = 0; i < 16; i++) {
            float4 a4 = *(float4*)&esm[r * EPI_PITCH + h * 64 + i * 4];
            float4 f  = fsrc[i];
            __half2 h0 = __floats2half2_rn(2.f * a4.x - f.x, 2.f * a4.y - f.y);
            __half2 h1 = __floats2half2_rn(2.f * a4.z - f.z, 2.f * a4.w - f.w);
            *(uint2*)(dst + i * 4) = make_uint2(*(uint32_t*)&h0, *(uint32_t*)&h1);
        }
    }
}

// ---------------------------------------------------------------------------
// Kernel 5: per-node output via mma.sync.
//   out[b,n,o] = sum_kc X[b,n,kc] * W_n[kc,o] + bias[n,o]
// Block = one node, 256 threads (8 warps: 4 b-groups x 2 o-groups).
// A = X [64 b][192 kc] fp16 (three 64x64 SW128 tiles), B = W [192 kc][64 o] fp16.
// B loaded with ldmatrix.trans (row-major [K][N]).
// ---------------------------------------------------------------------------
#define FG_A_OFF   0       // 3 * 8192 = 24576
#define FG_B_OFF   24576   // 192 * 128 = 24576
#define FG_BIAS    49152   // 64 floats
#define FG_SMEM    49664
#define FG_OPITCH  68

__global__ void __launch_bounds__(256) final_gconv(
    const float* __restrict__ E,
    const float* __restrict__ biasP,
    float* __restrict__ out)
{
    extern __shared__ char smem_raw[];
    char* sal = (char*)(((uintptr_t)smem_raw + 1023) & ~(uintptr_t)1023);
    const uint32_t sb = smem_u32(sal);

    const int n    = blockIdx.x;
    const int t    = threadIdx.x;
    const int lane = t & 31;
    const int wid  = t >> 5;
    const int wm   = wid >> 1;   // 0..3 : b rows wm*16
    const int wn   = wid & 1;    // 0..1 : o cols wn*32

    float* bias_s = (float*)(sal + FG_BIAS);

    // bias[o] = sum_d E[n,d] * biasP[d,o]
    if (t < OO) {
        float s = 0.f;
#pragma unroll
        for (int d = 0; d < DD; d++) s += E[n * DD + d] * biasP[d * OO + t];
        bias_s[t] = s;
    }

    // ---- load A tiles (feat_h, Y1h, Y2h), each 64 rows x 128B, SW128 ----
    {
        const __half* srcs[KK] = { g_Fh, g_Y1h, g_Y2h };
#pragma unroll
        for (int k = 0; k < KK; k++) {
            const __half* src = srcs[k];
#pragma unroll
            for (int i = 0; i < 2; i++) {
                int idx = t + i * 256;        // 0..511
                int row = idx >> 3;           // b
                int cu  = idx & 7;
                uint32_t so = SWZ((uint32_t)(row * 128 + cu * 16));
                *(uint4*)(sal + FG_A_OFF + k * 8192 + so) =
                    *((const uint4*)(src + ((size_t)row * NN + n) * CC) + cu);
            }
        }
    }
    // ---- load B tile: W_n [192][64] fp16, rows of 128B, SW128 ----
    {
        const __half* wsrc = g_Wh + (size_t)n * WCOLS;
#pragma unroll
        for (int i = 0; i < 6; i++) {
            int idx = t + i * 256;            // 0..1535
            int row = idx >> 3;               // kc
            int cu  = idx & 7;
            uint32_t so = SWZ((uint32_t)(row * 128 + cu * 16));
            *(uint4*)(sal + FG_B_OFF + so) = *((const uint4*)(wsrc + row * CC) + cu);
        }
    }
    __syncthreads();

    float acc[4][4];
#pragma unroll
    for (int j = 0; j < 4; j++)
#pragma unroll
        for (int q = 0; q < 4; q++) acc[j][q] = 0.f;

    const int a_row  = lane & 15;
    const int a_kofs = (lane >> 4) << 4;
    const int bt_row = lane & 15;             // kc within 16
    const int bt_col = (lane >> 4) << 3;      // o offset within 16

#pragma unroll
    for (int kk = 0; kk < 12; kk++) {
        const int kt  = kk >> 2;              // which A tile (k of cheb)
        const int kko = kk & 3;               // 16-k group within tile
        uint32_t a[4], b[2][4];
        ldsm4(a, sb + FG_A_OFF + kt * 8192 +
                  SWZ((uint32_t)((wm * 16 + a_row) * 128 + kko * 32 + a_kofs)));
#pragma unroll
        for (int j = 0; j < 2; j++) {
            uint32_t brow = (uint32_t)(kk * 16 + bt_row);
            uint32_t bcol = (uint32_t)(wn * 32 + j * 16 + bt_col);
            ldsm4t(b[j], sb + FG_B_OFF + SWZ(brow * 128 + bcol * 2));
        }
#pragma unroll
        for (int j = 0; j < 2; j++) {
            mma16816(acc[j * 2 + 0], a, &b[j][0]);
            mma16816(acc[j * 2 + 1], a, &b[j][2]);
        }
    }
    __syncthreads();

    // ---- stage to smem, add bias, coalesced store ----
    float* osm = (float*)sal;
#pragma unroll
    for (int nf = 0; nf < 4; nf++) {
        int r = wm * 16 + (lane >> 2);
        int c = wn * 32 + nf * 8 + (lane & 3) * 2;
        osm[r * FG_OPITCH + c]           = acc[nf][0];
        osm[r * FG_OPITCH + c + 1]       = acc[nf][1];
        osm[(r + 8) * FG_OPITCH + c]     = acc[nf][2];
        osm[(r + 8) * FG_OPITCH + c + 1] = acc[nf][3];
    }
    __syncthreads();

    const int b  = t >> 2;
    const int q0 = (t & 3) * 16;
    float* dst = out + ((size_t)b * NN + n) * OO + q0;
#pragma unroll
    for (int i = 0; i < 4; i++) {
        float4 v = *(float4*)&osm[b * FG_OPITCH + q0 + i * 4];
        v.x += bias_s[q0 + i * 4 + 0];
        v.y += bias_s[q0 + i * 4 + 1];
        v.z += bias_s[q0 + i * 4 + 2];
        v.w += bias_s[q0 + i * 4 + 3];
        *(float4*)(dst + i * 4) = v;
    }
}

// ---------------------------------------------------------------------------
extern "C" void kernel_launch(void* const* d_in, const int* in_sizes, int n_in,
                              void* d_out, int out_size)
{
    const float* E     = (const float*)d_in[0];  // [2048,16]
    const float* feat  = (const float*)d_in[1];  // [64,2048,64]
    const float* Wp    = (const float*)d_in[2];  // [16,3,64,64]
    const float* biasP = (const float*)d_in[3];  // [16,64]
    float* out = (float*)d_out;                  // [64,2048,64]

    cudaFuncSetAttribute(gemm_mma<0>, cudaFuncAttributeMaxDynamicSharedMemorySize, GEMM_SMEM);
    cudaFuncSetAttribute(gemm_mma<1>, cudaFuncAttributeMaxDynamicSharedMemorySize, GEMM_SMEM);
    cudaFuncSetAttribute(final_gconv, cudaFuncAttributeMaxDynamicSharedMemorySize, FG_SMEM);

    adj_softmax<<<NN, 256>>>(E);
    feat_transpose<<<dim3(NN / 64, BB), 256>>>(feat);
    compute_weights<<<dim3(WCOLS / 128, NN / 64), 256>>>(E, Wp);
    gemm_mma<0><<<dim3(NN / MT, BC / NT), 256, GEMM_SMEM>>>(feat);
    gemm_mma<1><<<dim3(NN / MT, BC / NT), 256, GEMM_SMEM>>>(feat);
    final_gconv<<<NN, 256, FG_SMEM>>>(E, biasP, out);
}